// round 1
// baseline (speedup 1.0000x reference)
#include <cuda_runtime.h>

// Problem constants
#define Sv   4096
#define Nv   262144
#define Ev   128
#define Hv   8
#define Dv   16
#define CKVv 64

// Scratch (device globals: no allocations allowed in kernel_launch)
__device__ __align__(16) float g_Weff[2 * Ev * CKVv];  // folded Wkv: [256][64]
__device__ __align__(16) float g_Q[Sv * Ev];           // Q = sp @ Wq.T
__device__ __align__(16) float g_ctx[Sv * Ev];         // softmax numerator sum(w*v)
__device__ float g_den[Sv * Hv];                       // softmax denominator sum(w)

// ---------------------------------------------------------------------------
// Kernel 0: zero accumulators + fold Wkv (exploit duplicated concat input)
// ---------------------------------------------------------------------------
__global__ void prep_kernel(const float* __restrict__ Wkv) {
    int tid = blockIdx.x * blockDim.x + threadIdx.x;
    int nt  = gridDim.x * blockDim.x;
    for (int i = tid; i < Sv * Ev; i += nt) g_ctx[i] = 0.f;
    for (int i = tid; i < Sv * Hv; i += nt) g_den[i] = 0.f;
    for (int i = tid; i < 2 * Ev * CKVv; i += nt) {
        int j = i >> 6;        // output row 0..255
        int c = i & 63;        // input col 0..63
        g_Weff[i] = Wkv[(j << 7) + c] + Wkv[(j << 7) + 64 + c];
    }
}

// ---------------------------------------------------------------------------
// Kernel 1: Q = sp @ Wq.T   (4096x128 @ 128x128) — tiny, keep simple.
// ---------------------------------------------------------------------------
__global__ void q_kernel(const float* __restrict__ sp, const float* __restrict__ Wq) {
    __shared__ float row[Ev];
    int j = threadIdx.x;
    const float4* wr4 = (const float4*)(Wq + (size_t)j * Ev);
    for (int s = blockIdx.x; s < Sv; s += gridDim.x) {
        __syncthreads();                    // protect row[] from previous iter
        row[j] = sp[(size_t)s * Ev + j];
        __syncthreads();
        float acc = 0.f;
        #pragma unroll
        for (int c4 = 0; c4 < Ev / 4; ++c4) {
            float4 w = wr4[c4];
            acc = fmaf(w.x, row[c4 * 4 + 0], acc);
            acc = fmaf(w.y, row[c4 * 4 + 1], acc);
            acc = fmaf(w.z, row[c4 * 4 + 2], acc);
            acc = fmaf(w.w, row[c4 * 4 + 3], acc);
        }
        g_Q[(size_t)s * Ev + j] = acc;
    }
}

// ---------------------------------------------------------------------------
// Main kernel: thread = point. x row (64 f32) in registers, W_eff in smem
// (uniform j,c across warp -> broadcast LDS.128). Computes k on the fly per
// head, score vs Q[seg], w = exp(score) (softmax shift-invariance -> no
// segment max needed), then v on the fly with atomic accumulation.
// ---------------------------------------------------------------------------
__device__ __forceinline__ float4 dot4rows(const float4* __restrict__ Wsh, int j,
                                           const float4* __restrict__ xr) {
    const float4* w0p = Wsh + (size_t)(j + 0) * (CKVv / 4);
    const float4* w1p = Wsh + (size_t)(j + 1) * (CKVv / 4);
    const float4* w2p = Wsh + (size_t)(j + 2) * (CKVv / 4);
    const float4* w3p = Wsh + (size_t)(j + 3) * (CKVv / 4);
    float a0 = 0.f, a1 = 0.f, a2 = 0.f, a3 = 0.f;
    #pragma unroll
    for (int c = 0; c < CKVv / 4; ++c) {
        float4 xv = xr[c];
        float4 w0 = w0p[c];
        float4 w1 = w1p[c];
        float4 w2 = w2p[c];
        float4 w3 = w3p[c];
        a0 = fmaf(w0.x, xv.x, a0); a0 = fmaf(w0.y, xv.y, a0);
        a0 = fmaf(w0.z, xv.z, a0); a0 = fmaf(w0.w, xv.w, a0);
        a1 = fmaf(w1.x, xv.x, a1); a1 = fmaf(w1.y, xv.y, a1);
        a1 = fmaf(w1.z, xv.z, a1); a1 = fmaf(w1.w, xv.w, a1);
        a2 = fmaf(w2.x, xv.x, a2); a2 = fmaf(w2.y, xv.y, a2);
        a2 = fmaf(w2.z, xv.z, a2); a2 = fmaf(w2.w, xv.w, a2);
        a3 = fmaf(w3.x, xv.x, a3); a3 = fmaf(w3.y, xv.y, a3);
        a3 = fmaf(w3.z, xv.z, a3); a3 = fmaf(w3.w, xv.w, a3);
    }
    return make_float4(a0, a1, a2, a3);
}

__global__ void __launch_bounds__(256, 2)
main_kernel(const float* __restrict__ xin, const int* __restrict__ assign,
            float* __restrict__ attn_out) {
    extern __shared__ float4 Wsh[];  // W_eff as float4: [256][16], 64 KB
    for (int i = threadIdx.x; i < 2 * Ev * CKVv / 4; i += blockDim.x)
        Wsh[i] = ((const float4*)g_Weff)[i];
    __syncthreads();

    int stride = gridDim.x * blockDim.x;
    for (int p = blockIdx.x * blockDim.x + threadIdx.x; p < Nv; p += stride) {
        float4 xr[CKVv / 4];
        const float4* xp = (const float4*)(xin + (size_t)p * CKVv);
        #pragma unroll
        for (int i = 0; i < CKVv / 4; ++i) xr[i] = xp[i];

        int seg = assign[p];
        const float4* Qrow = (const float4*)(g_Q + (size_t)seg * Ev);
        float* cbase = g_ctx + (size_t)seg * Ev;
        float* dbase = g_den + (size_t)seg * Hv;

        float ssum = 0.f;
        for (int h = 0; h < Hv; ++h) {
            float sc = 0.f;
            for (int d4 = 0; d4 < 4; ++d4) {
                float4 k = dot4rows(Wsh, h * 16 + d4 * 4, xr);
                float4 q = Qrow[h * 4 + d4];
                sc += q.x * k.x + q.y * k.y + q.z * k.z + q.w * k.w;
            }
            sc *= 0.25f;       // D^-0.5
            ssum += sc;
            float wv = __expf(sc);
            atomicAdd(dbase + h, wv);
            for (int d4 = 0; d4 < 4; ++d4) {
                float4 v = dot4rows(Wsh, Ev + h * 16 + d4 * 4, xr);
                int o = h * 16 + d4 * 4;
                atomicAdd(cbase + o + 0, v.x * wv);
                atomicAdd(cbase + o + 1, v.y * wv);
                atomicAdd(cbase + o + 2, v.z * wv);
                atomicAdd(cbase + o + 3, v.w * wv);
            }
        }
        attn_out[p] = ssum * 0.125f;  // mean over 8 heads
    }
}

// ---------------------------------------------------------------------------
// Finalize: context = ctx_num/denom, residual add, LayerNorm. One warp per row.
// ---------------------------------------------------------------------------
__global__ void finalize_kernel(const float* __restrict__ sp,
                                const float* __restrict__ lnw,
                                const float* __restrict__ lnb,
                                float* __restrict__ out) {
    int s = blockIdx.x * (blockDim.x >> 5) + (threadIdx.x >> 5);
    int lane = threadIdx.x & 31;
    if (s >= Sv) return;
    float4 spv = ((const float4*)(sp + (size_t)s * Ev))[lane];
    float4 cv  = ((const float4*)(g_ctx + (size_t)s * Ev))[lane];
    float den  = g_den[s * Hv + (lane >> 2)];
    float inv  = den > 0.f ? 1.f / den : 0.f;
    float x0 = spv.x + cv.x * inv;
    float x1 = spv.y + cv.y * inv;
    float x2 = spv.z + cv.z * inv;
    float x3 = spv.w + cv.w * inv;
    float ss = x0 + x1 + x2 + x3;
    #pragma unroll
    for (int o = 16; o; o >>= 1) ss += __shfl_xor_sync(0xffffffffu, ss, o);
    float mu = ss * (1.f / Ev);
    float d0 = x0 - mu, d1 = x1 - mu, d2 = x2 - mu, d3 = x3 - mu;
    float sq = d0 * d0 + d1 * d1 + d2 * d2 + d3 * d3;
    #pragma unroll
    for (int o = 16; o; o >>= 1) sq += __shfl_xor_sync(0xffffffffu, sq, o);
    float rstd = rsqrtf(sq * (1.f / Ev) + 1e-5f);
    float4 wv = ((const float4*)lnw)[lane];
    float4 bv = ((const float4*)lnb)[lane];
    float4 o4;
    o4.x = d0 * rstd * wv.x + bv.x;
    o4.y = d1 * rstd * wv.y + bv.y;
    o4.z = d2 * rstd * wv.z + bv.z;
    o4.w = d3 * rstd * wv.w + bv.w;
    ((float4*)(out + (size_t)s * Ev))[lane] = o4;
}

// ---------------------------------------------------------------------------
// Launch. Inputs (metadata order): sp_feat, rawPoint_feat, point_assignments,
// Wq, Wkv, ln_w, ln_b. Output: [updated_sp_feat (S*E) | attn_scores (N)] f32.
// ---------------------------------------------------------------------------
extern "C" void kernel_launch(void* const* d_in, const int* in_sizes, int n_in,
                              void* d_out, int out_size) {
    const float* sp     = (const float*)d_in[0];
    const float* xin    = (const float*)d_in[1];
    const int*   assign = (const int*)d_in[2];
    const float* Wq     = (const float*)d_in[3];
    const float* Wkv    = (const float*)d_in[4];
    const float* lnw    = (const float*)d_in[5];
    const float* lnb    = (const float*)d_in[6];
    float* out      = (float*)d_out;
    float* attn_out = out + (size_t)Sv * Ev;

    prep_kernel<<<128, 256>>>(Wkv);
    q_kernel<<<256, 128>>>(sp, Wq);

    int smem = 2 * Ev * CKVv * (int)sizeof(float);  // 64 KB dynamic smem
    cudaFuncSetAttribute(main_kernel, cudaFuncAttributeMaxDynamicSharedMemorySize, smem);
    main_kernel<<<296, 256, smem>>>(xin, assign, attn_out);

    finalize_kernel<<<Sv / 8, 256>>>(sp, lnw, lnb, out);
}

// round 3
// speedup vs baseline: 2.8544x; 2.8544x over previous
#include <cuda_runtime.h>

// Problem constants
#define Sv   4096
#define Nv   262144
#define Ev   128
#define Hv   8
#define Dv   16
#define CKVv 64
#define QKD  512      // Hv * CKVv
#define XPAD 68       // x_s row stride (floats), 16B-aligned, caps conflicts at 4-way

// Device scratch (no allocations allowed)
__device__ __align__(16) float g_Weff[2 * Ev * CKVv];  // folded Wkv: [256][64]
__device__ __align__(16) float g_Q[Sv * Ev];           // Q = sp @ Wq.T
__device__ __align__(16) float g_qk[Sv * QKD];         // folded per-segment query: [S][8][64]
__device__ int g_cnt[Sv];
__device__ int g_offs[Sv + 1];
__device__ int g_cursor[Sv];
__device__ int g_order[Nv];

// ---------------------------------------------------------------------------
// prep: fold Wkv (concat([x,x]) @ Wkv.T == x @ (Wkv[:, :64]+Wkv[:, 64:]).T),
// zero histogram
// ---------------------------------------------------------------------------
__global__ void prep_kernel(const float* __restrict__ Wkv) {
    int tid = blockIdx.x * blockDim.x + threadIdx.x;
    int nt  = gridDim.x * blockDim.x;
    for (int i = tid; i < Sv; i += nt) g_cnt[i] = 0;
    for (int i = tid; i < 2 * Ev * CKVv; i += nt) {
        int j = i >> 6;  // row 0..255
        int c = i & 63;  // col 0..63
        g_Weff[i] = Wkv[(j << 7) + c] + Wkv[(j << 7) + 64 + c];
    }
}

// ---------------------------------------------------------------------------
// Q = sp @ Wq.T  (4096x128 @ 128x128)
// ---------------------------------------------------------------------------
__global__ void q_kernel(const float* __restrict__ sp, const float* __restrict__ Wq) {
    __shared__ float row[Ev];
    int j = threadIdx.x;
    const float4* wr4 = (const float4*)(Wq + (size_t)j * Ev);
    for (int s = blockIdx.x; s < Sv; s += gridDim.x) {
        __syncthreads();
        row[j] = sp[(size_t)s * Ev + j];
        __syncthreads();
        float acc = 0.f;
        #pragma unroll
        for (int c4 = 0; c4 < Ev / 4; ++c4) {
            float4 w = wr4[c4];
            acc = fmaf(w.x, row[c4 * 4 + 0], acc);
            acc = fmaf(w.y, row[c4 * 4 + 1], acc);
            acc = fmaf(w.z, row[c4 * 4 + 2], acc);
            acc = fmaf(w.w, row[c4 * 4 + 3], acc);
        }
        g_Q[(size_t)s * Ev + j] = acc;
    }
}

// ---------------------------------------------------------------------------
// qk[seg][h][c] = 0.25 * sum_d Q[seg][h][d] * Wk_eff[h*16+d][c]
// grid = Sv, block = 128 (thread t -> h = t>>4, c4 = t&15, 4 outputs)
// ---------------------------------------------------------------------------
__global__ void qk_kernel() {
    __shared__ float Qs[Ev];
    int s = blockIdx.x, t = threadIdx.x;
    Qs[t] = g_Q[(size_t)s * Ev + t];
    __syncthreads();
    int h = t >> 4, c4 = t & 15;
    float4 acc = make_float4(0.f, 0.f, 0.f, 0.f);
    #pragma unroll
    for (int d = 0; d < Dv; ++d) {
        float q = Qs[h * Dv + d];
        float4 w = *(const float4*)&g_Weff[(h * Dv + d) * CKVv + c4 * 4];
        acc.x = fmaf(q, w.x, acc.x);
        acc.y = fmaf(q, w.y, acc.y);
        acc.z = fmaf(q, w.z, acc.z);
        acc.w = fmaf(q, w.w, acc.w);
    }
    acc.x *= 0.25f; acc.y *= 0.25f; acc.z *= 0.25f; acc.w *= 0.25f;
    *(float4*)&g_qk[(size_t)s * QKD + h * CKVv + c4 * 4] = acc;
}

// ---------------------------------------------------------------------------
// Counting sort: histogram -> exclusive scan -> scatter
// ---------------------------------------------------------------------------
__global__ void hist_kernel(const int* __restrict__ assign) {
    int tid = blockIdx.x * blockDim.x + threadIdx.x;
    int nt  = gridDim.x * blockDim.x;
    for (int p = tid; p < Nv; p += nt) atomicAdd(&g_cnt[assign[p]], 1);
}

__global__ void scan_kernel() {   // 1 block, 1024 threads; 4 bins each
    __shared__ int part[1024];
    int t = threadIdx.x;
    int c0 = g_cnt[4 * t + 0], c1 = g_cnt[4 * t + 1];
    int c2 = g_cnt[4 * t + 2], c3 = g_cnt[4 * t + 3];
    int sum = c0 + c1 + c2 + c3;
    part[t] = sum;
    __syncthreads();
    for (int off = 1; off < 1024; off <<= 1) {
        int add = (t >= off) ? part[t - off] : 0;
        __syncthreads();
        part[t] += add;
        __syncthreads();
    }
    int excl = part[t] - sum;
    int o0 = excl, o1 = o0 + c0, o2 = o1 + c1, o3 = o2 + c2;
    g_offs[4 * t + 0] = o0;  g_cursor[4 * t + 0] = o0;
    g_offs[4 * t + 1] = o1;  g_cursor[4 * t + 1] = o1;
    g_offs[4 * t + 2] = o2;  g_cursor[4 * t + 2] = o2;
    g_offs[4 * t + 3] = o3;  g_cursor[4 * t + 3] = o3;
    if (t == 1023) g_offs[Sv] = o3 + c3;
}

__global__ void scatter_kernel(const int* __restrict__ assign) {
    int tid = blockIdx.x * blockDim.x + threadIdx.x;
    int nt  = gridDim.x * blockDim.x;
    for (int p = tid; p < Nv; p += nt) {
        int s = assign[p];
        int pos = atomicAdd(&g_cursor[s], 1);
        g_order[pos] = p;
    }
}

// ---------------------------------------------------------------------------
// Segment kernel: one block (128 threads) per segment.
//  phase 1: thread = point; score_h = dot(qk[h], x_p); w = exp(score)
//  phase 2: thread = (h, c4); A[h][c] += w_{p,h} * x_p[c]  (registers)
//  tail:    ctx[h][d] = (A[h] . Wv_eff[h*16+d]) / den; residual + LayerNorm
// No floating-point atomics anywhere.
// ---------------------------------------------------------------------------
__global__ void __launch_bounds__(128)
seg_kernel(const float* __restrict__ xin, const float* __restrict__ sp,
           const float* __restrict__ lnw, const float* __restrict__ lnb,
           float* __restrict__ out, float* __restrict__ attn_out) {
    __shared__ float x_s[128 * XPAD];  // 34816 B
    __shared__ float qk_s[QKD];        // 2 KB
    __shared__ float w_s[128 * Hv];    // 4 KB
    __shared__ float A_s[Hv * XPAD];
    __shared__ float den_s[Hv];
    __shared__ float red_s[4];

    int s = blockIdx.x, t = threadIdx.x;
    int lane = t & 31, warp = t >> 5;

    // load per-segment folded query
    ((float4*)qk_s)[t] = ((const float4*)(g_qk + (size_t)s * QKD))[t];

    int start = g_offs[s], end = g_offs[s + 1];
    int h = t >> 4, c4 = t & 15;
    float4 A = make_float4(0.f, 0.f, 0.f, 0.f);
    float den = 0.f;
    __syncthreads();

    for (int base = start; base < end; base += 128) {
        int P = min(128, end - base);
        // stage x rows for this chunk (coalesced 256B per row)
        for (int idx = t; idx < P * 16; idx += 128) {
            int r = idx >> 4, cc = idx & 15;
            int p = g_order[base + r];
            float4 v = ((const float4*)xin)[(size_t)p * 16 + cc];
            *(float4*)&x_s[r * XPAD + cc * 4] = v;
        }
        __syncthreads();

        // phase 1: one thread per point
        if (t < P) {
            float xr[CKVv];
            #pragma unroll
            for (int i = 0; i < 16; ++i) {
                float4 v = *(const float4*)&x_s[t * XPAD + i * 4];
                xr[4 * i + 0] = v.x; xr[4 * i + 1] = v.y;
                xr[4 * i + 2] = v.z; xr[4 * i + 3] = v.w;
            }
            float ssum = 0.f;
            #pragma unroll
            for (int hh = 0; hh < Hv; ++hh) {
                float sc = 0.f;
                const float4* qv4 = (const float4*)(qk_s + hh * CKVv);
                #pragma unroll
                for (int i = 0; i < 16; ++i) {
                    float4 q = qv4[i];
                    sc = fmaf(q.x, xr[4 * i + 0], sc);
                    sc = fmaf(q.y, xr[4 * i + 1], sc);
                    sc = fmaf(q.z, xr[4 * i + 2], sc);
                    sc = fmaf(q.w, xr[4 * i + 3], sc);
                }
                ssum += sc;
                w_s[t * Hv + hh] = __expf(sc);
            }
            attn_out[g_order[base + t]] = ssum * 0.125f;
        }
        __syncthreads();

        // phase 2: thread (h, c4) accumulates A over chunk points
        for (int p = 0; p < P; ++p) {
            float wv = w_s[p * Hv + h];
            float4 xv = *(const float4*)&x_s[p * XPAD + c4 * 4];
            A.x = fmaf(wv, xv.x, A.x);
            A.y = fmaf(wv, xv.y, A.y);
            A.z = fmaf(wv, xv.z, A.z);
            A.w = fmaf(wv, xv.w, A.w);
            if (c4 == 0) den += wv;
        }
        __syncthreads();   // protect x_s/w_s before next chunk restage
    }

    // publish A to smem
    *(float4*)&A_s[h * XPAD + c4 * 4] = A;
    if (c4 == 0) den_s[h] = den;
    __syncthreads();

    // tail: thread t = output dim e = h*16 + d;  Wv row = 128 + t
    const float4* wvr = (const float4*)(g_Weff + (size_t)(Ev + t) * CKVv);
    const float4* av4 = (const float4*)(A_s + h * XPAD);
    float acc = 0.f;
    #pragma unroll
    for (int i = 0; i < 16; ++i) {
        float4 w4 = wvr[i];
        float4 a4 = av4[i];
        acc = fmaf(w4.x, a4.x, acc);
        acc = fmaf(w4.y, a4.y, acc);
        acc = fmaf(w4.z, a4.z, acc);
        acc = fmaf(w4.w, a4.w, acc);
    }
    float dd  = den_s[h];
    float ctx = dd > 0.f ? acc / dd : 0.f;
    float xval = sp[(size_t)s * Ev + t] + ctx;

    // LayerNorm across 128 threads (4 warps)
    float v = xval;
    #pragma unroll
    for (int o = 16; o; o >>= 1) v += __shfl_xor_sync(0xffffffffu, v, o);
    if (lane == 0) red_s[warp] = v;
    __syncthreads();
    float tot = red_s[0] + red_s[1] + red_s[2] + red_s[3];
    float mu = tot * (1.f / Ev);
    float dv = xval - mu;
    __syncthreads();
    float sq = dv * dv;
    #pragma unroll
    for (int o = 16; o; o >>= 1) sq += __shfl_xor_sync(0xffffffffu, sq, o);
    if (lane == 0) red_s[warp] = sq;
    __syncthreads();
    float tot2 = red_s[0] + red_s[1] + red_s[2] + red_s[3];
    float rstd = rsqrtf(tot2 * (1.f / Ev) + 1e-5f);
    out[(size_t)s * Ev + t] = dv * rstd * lnw[t] + lnb[t];
}

// ---------------------------------------------------------------------------
// Launch. Inputs (metadata order): sp_feat, rawPoint_feat, point_assignments,
// Wq, Wkv, ln_w, ln_b. Output: [updated_sp_feat (S*E) | attn_scores (N)] f32.
// ---------------------------------------------------------------------------
extern "C" void kernel_launch(void* const* d_in, const int* in_sizes, int n_in,
                              void* d_out, int out_size) {
    const float* sp     = (const float*)d_in[0];
    const float* xin    = (const float*)d_in[1];
    const int*   assign = (const int*)d_in[2];
    const float* Wq     = (const float*)d_in[3];
    const float* Wkv    = (const float*)d_in[4];
    const float* lnw    = (const float*)d_in[5];
    const float* lnb    = (const float*)d_in[6];
    float* out      = (float*)d_out;
    float* attn_out = out + (size_t)Sv * Ev;

    prep_kernel<<<128, 256>>>(Wkv);
    q_kernel<<<256, 128>>>(sp, Wq);
    qk_kernel<<<Sv, 128>>>();
    hist_kernel<<<256, 256>>>(assign);
    scan_kernel<<<1, 1024>>>();
    scatter_kernel<<<256, 256>>>(assign);
    seg_kernel<<<Sv, 128>>>(xin, sp, lnw, lnb, out, attn_out);
}